// round 2
// baseline (speedup 1.0000x reference)
#include <cuda_runtime.h>
#include <math.h>

#define BSZ 64
#define MM  2048
#define DD  1024
#define HH  1024
#define HT  8            // H / 128 tiles

#define BM 128
#define BN 128
#define BK 16

// Scratch (device globals: allocation-free rule)
__device__ float g_qproj[BSZ * HH];          // 256 KB
__device__ float g_part[HT * BSZ * MM];      // 4 MB: per-hTile partial attn logits

// ---------------------------------------------------------------------------
// Kernel 1: q_proj[b,h] = query[b,:] . Wq[h,:] + bq[h]
// grid (BSZ, HH/128), block 128 (4 warps, one h per warp per step)
// ---------------------------------------------------------------------------
__global__ __launch_bounds__(128) void qproj_kernel(
    const float* __restrict__ query,
    const float* __restrict__ Wq,
    const float* __restrict__ bq)
{
    __shared__ float qs[DD];
    const int b  = blockIdx.x;
    const int h0 = blockIdx.y * 128;
    const int tid = threadIdx.x;

    for (int i = tid; i < DD; i += 128) qs[i] = query[b * DD + i];
    __syncthreads();

    const int warp = tid >> 5, lane = tid & 31;
    for (int hl = warp; hl < 128; hl += 4) {
        const int h = h0 + hl;
        const float* w = Wq + (size_t)h * DD;
        float s = 0.f;
        #pragma unroll 8
        for (int j = lane; j < DD; j += 32) s += qs[j] * w[j];
        #pragma unroll
        for (int off = 16; off > 0; off >>= 1)
            s += __shfl_xor_sync(0xffffffffu, s, off);
        if (lane == 0) g_qproj[b * HH + h] = s + bq[h];
    }
}

// ---------------------------------------------------------------------------
// Kernel 2: fused  m_proj GEMM + tanh + dot(v)  -> g_part[hTile][row]
//   C[row,h] = sum_d memory[row,d] * Wm[h,d]
//   partial_attn[row] += sum_h tanh(C + qproj[b,h]) * v[h]   (h in this tile)
// 128x128 tile, BK=16, 256 threads, 8x8 microtile.
// ---------------------------------------------------------------------------
__global__ __launch_bounds__(256) void fused_attn_gemm_kernel(
    const float* __restrict__ A,    // memory [BSZ*MM, DD]
    const float* __restrict__ B,    // Wm     [HH, DD]
    const float* __restrict__ v)    // [HH]
{
    __shared__ float As[BK * BM];       // transposed: As[k][row]
    __shared__ float Bs[BK * BN];       // transposed: Bs[k][h]
    __shared__ float red[BM * 16];

    const int tid = threadIdx.x;
    const int ty = tid >> 4;            // 0..15
    const int tx = tid & 15;            // 0..15
    const int row0 = blockIdx.y * BM;
    const int h0   = blockIdx.x * BN;

    const int lr = tid >> 2;            // 0..63  (load row)
    const int lc = (tid & 3) * 4;       // 0,4,8,12 (load col group)

    const float* Ab = A + (size_t)row0 * DD;
    const float* Bb = B + (size_t)h0 * DD;

    float acc[8][8];
    #pragma unroll
    for (int i = 0; i < 8; i++)
        #pragma unroll
        for (int j = 0; j < 8; j++) acc[i][j] = 0.f;

    for (int k0 = 0; k0 < DD; k0 += BK) {
        // stage global loads into registers
        const float4 a0 = *(const float4*)(Ab + (size_t)lr        * DD + k0 + lc);
        const float4 a1 = *(const float4*)(Ab + (size_t)(lr + 64) * DD + k0 + lc);
        const float4 b0 = *(const float4*)(Bb + (size_t)lr        * DD + k0 + lc);
        const float4 b1 = *(const float4*)(Bb + (size_t)(lr + 64) * DD + k0 + lc);

        __syncthreads();   // previous tile's compute done
        As[(lc + 0) * BM + lr] = a0.x;  As[(lc + 1) * BM + lr] = a0.y;
        As[(lc + 2) * BM + lr] = a0.z;  As[(lc + 3) * BM + lr] = a0.w;
        As[(lc + 0) * BM + lr + 64] = a1.x;  As[(lc + 1) * BM + lr + 64] = a1.y;
        As[(lc + 2) * BM + lr + 64] = a1.z;  As[(lc + 3) * BM + lr + 64] = a1.w;
        Bs[(lc + 0) * BN + lr] = b0.x;  Bs[(lc + 1) * BN + lr] = b0.y;
        Bs[(lc + 2) * BN + lr] = b0.z;  Bs[(lc + 3) * BN + lr] = b0.w;
        Bs[(lc + 0) * BN + lr + 64] = b1.x;  Bs[(lc + 1) * BN + lr + 64] = b1.y;
        Bs[(lc + 2) * BN + lr + 64] = b1.z;  Bs[(lc + 3) * BN + lr + 64] = b1.w;
        __syncthreads();

        #pragma unroll
        for (int kk = 0; kk < BK; kk++) {
            float af[8], bf[8];
            float4 av0 = *(const float4*)&As[kk * BM + ty * 8];
            float4 av1 = *(const float4*)&As[kk * BM + ty * 8 + 4];
            float4 bv0 = *(const float4*)&Bs[kk * BN + tx * 8];
            float4 bv1 = *(const float4*)&Bs[kk * BN + tx * 8 + 4];
            af[0]=av0.x; af[1]=av0.y; af[2]=av0.z; af[3]=av0.w;
            af[4]=av1.x; af[5]=av1.y; af[6]=av1.z; af[7]=av1.w;
            bf[0]=bv0.x; bf[1]=bv0.y; bf[2]=bv0.z; bf[3]=bv0.w;
            bf[4]=bv1.x; bf[5]=bv1.y; bf[6]=bv1.z; bf[7]=bv1.w;
            #pragma unroll
            for (int i = 0; i < 8; i++)
                #pragma unroll
                for (int j = 0; j < 8; j++)
                    acc[i][j] += af[i] * bf[j];
        }
    }

    // Epilogue: tanh(acc + qproj) . v  -> per-row partial
    const int batch = row0 >> 11;      // row0 / MM, MM = 2048
    float qp[8], vv[8];
    #pragma unroll
    for (int j = 0; j < 8; j++) {
        const int h = h0 + tx * 8 + j;
        qp[j] = g_qproj[batch * HH + h];
        vv[j] = v[h];
    }
    __syncthreads();   // done with As/Bs usage pattern; safe before red writes
    #pragma unroll
    for (int i = 0; i < 8; i++) {
        float p = 0.f;
        #pragma unroll
        for (int j = 0; j < 8; j++)
            p += tanhf(acc[i][j] + qp[j]) * vv[j];
        red[(ty * 8 + i) * 16 + tx] = p;
    }
    __syncthreads();
    if (tid < BM) {
        float s = 0.f;
        #pragma unroll
        for (int t = 0; t < 16; t++) s += red[tid * 16 + t];
        g_part[blockIdx.x * (BSZ * MM) + row0 + tid] = s;
    }
}

// ---------------------------------------------------------------------------
// Kernel 3: sum h-tile partials, softmax over M per batch -> weights (d_out)
// ---------------------------------------------------------------------------
__global__ __launch_bounds__(256) void softmax_kernel(float* __restrict__ out_w)
{
    __shared__ float sm[MM];
    __shared__ float red[256];
    const int b = blockIdx.x, tid = threadIdx.x;

    float lmax = -1e30f;
    for (int m = tid; m < MM; m += 256) {
        float s = 0.f;
        #pragma unroll
        for (int t = 0; t < HT; t++) s += g_part[t * (BSZ * MM) + b * MM + m];
        sm[m] = s;
        lmax = fmaxf(lmax, s);
    }
    red[tid] = lmax; __syncthreads();
    for (int off = 128; off > 0; off >>= 1) {
        if (tid < off) red[tid] = fmaxf(red[tid], red[tid + off]);
        __syncthreads();
    }
    const float mx = red[0];
    __syncthreads();

    float lsum = 0.f;
    for (int m = tid; m < MM; m += 256) {
        const float e = expf(sm[m] - mx);
        sm[m] = e;
        lsum += e;
    }
    red[tid] = lsum; __syncthreads();
    for (int off = 128; off > 0; off >>= 1) {
        if (tid < off) red[tid] += red[tid + off];
        __syncthreads();
    }
    const float inv = 1.f / red[0];
    for (int m = tid; m < MM; m += 256)
        out_w[b * MM + m] = sm[m] * inv;
}

// ---------------------------------------------------------------------------
// Kernel 4: weighted_memory[b,d] = sum_m w[b,m] * memory[b,m,d]
// grid (DD/128, BSZ), 256 threads = 128 d-lanes x 2 m-groups
// ---------------------------------------------------------------------------
__global__ __launch_bounds__(256) void weighted_mem_kernel(
    const float* __restrict__ mem,
    const float* __restrict__ weights,
    float* __restrict__ out_wm)
{
    __shared__ float wsh[MM];
    __shared__ float red[256];
    const int b = blockIdx.y;
    const int d0 = blockIdx.x * 128;
    const int tid = threadIdx.x;

    for (int i = tid; i < MM; i += 256) wsh[i] = weights[b * MM + i];
    __syncthreads();

    const int dl = tid & 127;
    const int grp = tid >> 7;
    const int d = d0 + dl;

    float acc = 0.f;
    for (int m = grp; m < MM; m += 2)
        acc += wsh[m] * mem[((size_t)(b * MM + m)) * DD + d];

    red[tid] = acc; __syncthreads();
    if (tid < 128)
        out_wm[b * DD + d] = red[tid] + red[tid + 128];
}

// ---------------------------------------------------------------------------
extern "C" void kernel_launch(void* const* d_in, const int* in_sizes, int n_in,
                              void* d_out, int out_size)
{
    const float* query  = (const float*)d_in[0];
    const float* memory = (const float*)d_in[1];
    const float* Wq     = (const float*)d_in[2];
    const float* bq     = (const float*)d_in[3];
    const float* Wm     = (const float*)d_in[4];
    const float* v      = (const float*)d_in[5];
    float* out = (float*)d_out;

    float* out_weights = out;                  // [BSZ, 1, MM]
    float* out_wmem    = out + BSZ * MM;       // [BSZ, 1, DD]

    qproj_kernel<<<dim3(BSZ, HH / 128), 128>>>(query, Wq, bq);
    fused_attn_gemm_kernel<<<dim3(HH / BN, (BSZ * MM) / BM), 256>>>(memory, Wm, v);
    softmax_kernel<<<BSZ, 256>>>(out_weights);
    weighted_mem_kernel<<<dim3(DD / 128, BSZ), 256>>>(memory, out_weights, out_wmem);
}

// round 4
// speedup vs baseline: 2.5171x; 2.5171x over previous
#include <cuda_runtime.h>
#include <cuda_bf16.h>
#include <math.h>
#include <stdint.h>

#define BSZ 64
#define MM  2048
#define DD  1024
#define HH  1024
#define HT  8                 // h-tiles (HH/128)
#define KC  64                // k per stage
#define NSTG (DD / KC)        // 16

// stage tile offsets (each 16 KB: 128 rows x 128B)
#define T_AHI 0
#define T_ALO 16384
#define T_BHI 32768
#define T_BLO 49152
#define STAGE_B 65536
#define OFF_QV   0
#define OFF_VV   512
#define OFF_RED  1024
#define OFF_TILE 2048
#define SMEM_TOTAL (OFF_TILE + 2 * STAGE_B)   // 133120 B

__device__ float g_qproj[BSZ * HH];
__device__ float g_part[HT * BSZ * MM];
__device__ __nv_bfloat16 g_bh[HH * DD];   // Wm hi image (k-major)
__device__ __nv_bfloat16 g_bl[HH * DD];   // Wm lo image

// ---------------------------------------------------------------------------
__device__ __forceinline__ uint32_t smem_u32(const void* p) {
    uint32_t a;
    asm("{ .reg .u64 t; cvta.to.shared.u64 t, %1; cvt.u32.u64 %0, t; }" : "=r"(a) : "l"(p));
    return a;
}
#define SW(o) ((o) ^ (((o) >> 3) & 0x70))

#define LDSM4(r, addr) \
    asm volatile("ldmatrix.sync.aligned.m8n8.x4.shared.b16 {%0,%1,%2,%3}, [%4];" \
        : "=r"((r)[0]), "=r"((r)[1]), "=r"((r)[2]), "=r"((r)[3]) : "r"(addr))

#define MMA16816(d, a, b0v, b1v) \
    asm volatile("mma.sync.aligned.m16n8k16.row.col.f32.bf16.bf16.f32 " \
        "{%0,%1,%2,%3}, {%4,%5,%6,%7}, {%8,%9}, {%0,%1,%2,%3};" \
        : "+f"((d)[0]), "+f"((d)[1]), "+f"((d)[2]), "+f"((d)[3]) \
        : "r"((a)[0]), "r"((a)[1]), "r"((a)[2]), "r"((a)[3]), "r"(b0v), "r"(b1v))

#define CP16(dst, src) \
    asm volatile("cp.async.cg.shared.global [%0], [%1], 16;" :: "r"(dst), "l"(src) : "memory")
#define CP_COMMIT asm volatile("cp.async.commit_group;" ::: "memory")
#define CP_WAIT0  asm volatile("cp.async.wait_group 0;"  ::: "memory")

__device__ __forceinline__ float tanh_fast(float x) {
    float e, r;
    asm("ex2.approx.f32 %0, %1;" : "=f"(e) : "f"(x * 2.8853900817779268f));   // e^{2x}
    asm("rcp.approx.f32 %0, %1;" : "=f"(r) : "f"(e + 1.0f));
    return fmaf(-2.0f, r, 1.0f);
}

// split 8 fp32 -> 16B hi (8 bf16) + 16B lo
__device__ __forceinline__ void split8(const float4 a, const float4 b,
                                       uint4& hi, uint4& lo) {
    __nv_bfloat162 h0 = __floats2bfloat162_rn(a.x, a.y);
    __nv_bfloat162 h1 = __floats2bfloat162_rn(a.z, a.w);
    __nv_bfloat162 h2 = __floats2bfloat162_rn(b.x, b.y);
    __nv_bfloat162 h3 = __floats2bfloat162_rn(b.z, b.w);
    __nv_bfloat162 l0 = __floats2bfloat162_rn(a.x - __bfloat162float(h0.x),
                                              a.y - __bfloat162float(h0.y));
    __nv_bfloat162 l1 = __floats2bfloat162_rn(a.z - __bfloat162float(h1.x),
                                              a.w - __bfloat162float(h1.y));
    __nv_bfloat162 l2 = __floats2bfloat162_rn(b.x - __bfloat162float(h2.x),
                                              b.y - __bfloat162float(h2.y));
    __nv_bfloat162 l3 = __floats2bfloat162_rn(b.z - __bfloat162float(h3.x),
                                              b.w - __bfloat162float(h3.y));
    hi = make_uint4(*(uint32_t*)&h0, *(uint32_t*)&h1, *(uint32_t*)&h2, *(uint32_t*)&h3);
    lo = make_uint4(*(uint32_t*)&l0, *(uint32_t*)&l1, *(uint32_t*)&l2, *(uint32_t*)&l3);
}

// ---------------------------------------------------------------------------
// Prep: Wm -> bf16 hi/lo images (k-major, plain layout)
// ---------------------------------------------------------------------------
__global__ __launch_bounds__(256) void prep_b_kernel(const float* __restrict__ Wm) {
    const int h = blockIdx.x;
    const int d = threadIdx.x * 8;
    const float4 a = *(const float4*)(Wm + (size_t)h * DD + d);
    const float4 b = *(const float4*)(Wm + (size_t)h * DD + d + 4);
    uint4 hi, lo;
    split8(a, b, hi, lo);
    *(uint4*)(g_bh + (size_t)h * DD + d) = hi;
    *(uint4*)(g_bl + (size_t)h * DD + d) = lo;
}

// ---------------------------------------------------------------------------
// qproj
// ---------------------------------------------------------------------------
__global__ __launch_bounds__(128) void qproj_kernel(
    const float* __restrict__ query, const float* __restrict__ Wq,
    const float* __restrict__ bq) {
    __shared__ float qs[DD];
    const int b = blockIdx.x, h0 = blockIdx.y * 128, tid = threadIdx.x;
    for (int i = tid; i < DD; i += 128) qs[i] = query[b * DD + i];
    __syncthreads();
    const int warp = tid >> 5, lane = tid & 31;
    for (int hl = warp; hl < 128; hl += 4) {
        const int h = h0 + hl;
        const float* w = Wq + (size_t)h * DD;
        float s = 0.f;
        #pragma unroll 8
        for (int j = lane; j < DD; j += 32) s += qs[j] * w[j];
        #pragma unroll
        for (int o = 16; o > 0; o >>= 1) s += __shfl_xor_sync(0xffffffffu, s, o);
        if (lane == 0) g_qproj[b * HH + h] = s + bq[h];
    }
}

// ---------------------------------------------------------------------------
// HMMA bf16 3-pass GEMM + fused tanh/dot epilogue
// grid (HT=8, 1024), 256 threads (8 warps: 4m x 2n, warp tile 32x64)
// ---------------------------------------------------------------------------
__global__ __launch_bounds__(256, 1) void attn_gemm_hmma(
    const float* __restrict__ A, const float* __restrict__ v) {
    extern __shared__ char smem[];
    const uint32_t sb = smem_u32(smem);
    const int tid = threadIdx.x;
    const int h0 = blockIdx.x * 128;
    const int row0 = blockIdx.y * 128;
    const int batch = row0 >> 11;

    float* qv = (float*)(smem + OFF_QV);
    float* vv = (float*)(smem + OFF_VV);
    float* sred = (float*)(smem + OFF_RED);
    if (tid < 128) {
        qv[tid] = g_qproj[batch * HH + h0 + tid];
        vv[tid] = v[h0 + tid];
    }

    // copy-thread mapping: 16B units; q = tid + 256*j; row = q>>3, cu = q&7
    const int crow = tid >> 3;          // 0..31 (+32 per j)
    const int ccu  = tid & 7;           // 16B unit within 128B row
    const float* Abase = A + (size_t)row0 * DD;
    const __nv_bfloat16* Bh0 = g_bh + (size_t)h0 * DD;
    const __nv_bfloat16* Bl0 = g_bl + (size_t)h0 * DD;

    const int warp = tid >> 5, lane = tid & 31;
    const int wm = (warp >> 1) * 32;
    const int wn = (warp & 1) * 64;
    const int lrow = lane & 15;
    const int lkb  = (lane >> 4) * 16;

    float acc[2][8][4];
    #pragma unroll
    for (int i = 0; i < 2; i++)
        #pragma unroll
        for (int j = 0; j < 8; j++)
            #pragma unroll
            for (int k = 0; k < 4; k++) acc[i][j][k] = 0.f;

    float4 av[4][2];

    // ---- prologue: stage 0 ----
    #pragma unroll
    for (int j = 0; j < 4; j++) {
        const int row = crow + 32 * j;
        const float* p = Abase + (size_t)row * DD + ccu * 8;
        av[j][0] = ((const float4*)p)[0];
        av[j][1] = ((const float4*)p)[1];
        const uint32_t o = SW((uint32_t)(row * 128 + ccu * 16));
        CP16(sb + OFF_TILE + T_BHI + o, Bh0 + (size_t)row * DD + ccu * 8);
        CP16(sb + OFF_TILE + T_BLO + o, Bl0 + (size_t)row * DD + ccu * 8);
    }
    CP_COMMIT;
    #pragma unroll
    for (int j = 0; j < 4; j++) {
        const int row = crow + 32 * j;
        const uint32_t o = SW((uint32_t)(row * 128 + ccu * 16));
        uint4 hi, lo;
        split8(av[j][0], av[j][1], hi, lo);
        *(uint4*)(smem + OFF_TILE + T_AHI + o) = hi;
        *(uint4*)(smem + OFF_TILE + T_ALO + o) = lo;
    }

    // ---- main loop ----
    for (int s = 0; s < NSTG; s++) {
        const int cur = s & 1;
        CP_WAIT0;
        __syncthreads();

        if (s + 1 < NSTG) {   // issue next-stage loads
            const int nxt = cur ^ 1;
            const uint32_t bb = sb + OFF_TILE + nxt * STAGE_B;
            #pragma unroll
            for (int j = 0; j < 4; j++) {
                const int row = crow + 32 * j;
                const float* p = Abase + (size_t)row * DD + (s + 1) * KC + ccu * 8;
                av[j][0] = ((const float4*)p)[0];
                av[j][1] = ((const float4*)p)[1];
                const uint32_t o = SW((uint32_t)(row * 128 + ccu * 16));
                CP16(bb + T_BHI + o, Bh0 + (size_t)row * DD + (s + 1) * KC + ccu * 8);
                CP16(bb + T_BLO + o, Bl0 + (size_t)row * DD + (s + 1) * KC + ccu * 8);
            }
            CP_COMMIT;
        }

        // compute stage cur
        const uint32_t base = sb + OFF_TILE + cur * STAGE_B;
        #pragma unroll
        for (int kk = 0; kk < 4; kk++) {
            uint32_t ah[2][4], al[2][4], bh4[4][4], bl4[4][4];
            #pragma unroll
            for (int mi = 0; mi < 2; mi++) {
                const uint32_t o =
                    SW((uint32_t)((wm + mi * 16 + lrow) * 128 + kk * 32 + lkb));
                LDSM4(ah[mi], base + T_AHI + o);
                LDSM4(al[mi], base + T_ALO + o);
            }
            #pragma unroll
            for (int g = 0; g < 4; g++) {
                const uint32_t o =
                    SW((uint32_t)((wn + g * 16 + lrow) * 128 + kk * 32 + lkb));
                LDSM4(bh4[g], base + T_BHI + o);
                LDSM4(bl4[g], base + T_BLO + o);
            }
            #pragma unroll
            for (int mi = 0; mi < 2; mi++)
                #pragma unroll
                for (int nj = 0; nj < 8; nj++) {
                    const int g = nj >> 1, sl = nj & 1;
                    MMA16816(acc[mi][nj], ah[mi], bh4[g][sl], bh4[g][sl + 2]);
                    MMA16816(acc[mi][nj], ah[mi], bl4[g][sl], bl4[g][sl + 2]);
                    MMA16816(acc[mi][nj], al[mi], bh4[g][sl], bh4[g][sl + 2]);
                }
        }

        if (s + 1 < NSTG) {   // store next-stage A (other buffer; safe pre-sync)
            const int nxt = cur ^ 1;
            char* bp = smem + OFF_TILE + nxt * STAGE_B;
            #pragma unroll
            for (int j = 0; j < 4; j++) {
                const int row = crow + 32 * j;
                const uint32_t o = SW((uint32_t)(row * 128 + ccu * 16));
                uint4 hi, lo;
                split8(av[j][0], av[j][1], hi, lo);
                *(uint4*)(bp + T_AHI + o) = hi;
                *(uint4*)(bp + T_ALO + o) = lo;
            }
        }
    }

    // ---- epilogue: tanh(c + qp) * v, row-reduce ----
    #pragma unroll
    for (int mi = 0; mi < 2; mi++)
        #pragma unroll
        for (int hf = 0; hf < 2; hf++) {
            float s = 0.f;
            #pragma unroll
            for (int nj = 0; nj < 8; nj++)
                #pragma unroll
                for (int c = 0; c < 2; c++) {
                    const int h = wn + nj * 8 + ((lane & 3) << 1) + c;
                    const float cc = acc[mi][nj][hf * 2 + c] + qv[h];
                    s += tanh_fast(cc) * vv[h];
                }
            s += __shfl_xor_sync(0xffffffffu, s, 1);
            s += __shfl_xor_sync(0xffffffffu, s, 2);
            if ((lane & 3) == 0)
                sred[(wm + mi * 16 + hf * 8 + (lane >> 2)) * 2 + (warp & 1)] = s;
        }
    __syncthreads();
    if (tid < 128)
        g_part[blockIdx.x * (BSZ * MM) + row0 + tid] = sred[tid * 2] + sred[tid * 2 + 1];
}

// ---------------------------------------------------------------------------
// softmax over M per batch (sums 8 h-tile partials)
// ---------------------------------------------------------------------------
__global__ __launch_bounds__(256) void softmax_kernel(float* __restrict__ out_w) {
    __shared__ float sm[MM];
    __shared__ float red[256];
    const int b = blockIdx.x, tid = threadIdx.x;
    float lmax = -1e30f;
    for (int m = tid; m < MM; m += 256) {
        float s = 0.f;
        #pragma unroll
        for (int t = 0; t < HT; t++) s += g_part[t * (BSZ * MM) + b * MM + m];
        sm[m] = s;
        lmax = fmaxf(lmax, s);
    }
    red[tid] = lmax; __syncthreads();
    for (int o = 128; o > 0; o >>= 1) {
        if (tid < o) red[tid] = fmaxf(red[tid], red[tid + o]);
        __syncthreads();
    }
    const float mx = red[0];
    __syncthreads();
    float ls = 0.f;
    for (int m = tid; m < MM; m += 256) {
        const float e = expf(sm[m] - mx);
        sm[m] = e; ls += e;
    }
    red[tid] = ls; __syncthreads();
    for (int o = 128; o > 0; o >>= 1) {
        if (tid < o) red[tid] += red[tid + o];
        __syncthreads();
    }
    const float inv = 1.f / red[0];
    for (int m = tid; m < MM; m += 256) out_w[b * MM + m] = sm[m] * inv;
}

// ---------------------------------------------------------------------------
// weighted_memory: float4, 8-way m-split
// ---------------------------------------------------------------------------
__global__ __launch_bounds__(256) void weighted_mem_kernel(
    const float* __restrict__ mem, const float* __restrict__ w,
    float* __restrict__ out) {
    __shared__ float wsh[MM];
    __shared__ float4 sred4[256];
    const int b = blockIdx.y, d0 = blockIdx.x * 128, tid = threadIdx.x;
    for (int i = tid; i < MM; i += 256) wsh[i] = w[b * MM + i];
    __syncthreads();
    const int lane = tid & 31, grp = tid >> 5;
    const float* base = mem + (size_t)b * MM * DD + d0 + lane * 4;
    float4 acc = make_float4(0.f, 0.f, 0.f, 0.f);
    #pragma unroll 4
    for (int m = grp; m < MM; m += 8) {
        const float ww = wsh[m];
        const float4 x = *(const float4*)(base + (size_t)m * DD);
        acc.x = fmaf(ww, x.x, acc.x); acc.y = fmaf(ww, x.y, acc.y);
        acc.z = fmaf(ww, x.z, acc.z); acc.w = fmaf(ww, x.w, acc.w);
    }
    sred4[tid] = acc;
    __syncthreads();
    if (tid < 32) {
        float4 s = sred4[tid];
        #pragma unroll
        for (int g = 1; g < 8; g++) {
            const float4 t = sred4[tid + g * 32];
            s.x += t.x; s.y += t.y; s.z += t.z; s.w += t.w;
        }
        *(float4*)(out + b * DD + d0 + tid * 4) = s;
    }
}

// ---------------------------------------------------------------------------
extern "C" void kernel_launch(void* const* d_in, const int* in_sizes, int n_in,
                              void* d_out, int out_size) {
    const float* query  = (const float*)d_in[0];
    const float* memory = (const float*)d_in[1];
    const float* Wq     = (const float*)d_in[2];
    const float* bq     = (const float*)d_in[3];
    const float* Wm     = (const float*)d_in[4];
    const float* v      = (const float*)d_in[5];
    float* out = (float*)d_out;
    float* out_weights = out;                // [BSZ,1,MM]
    float* out_wmem    = out + BSZ * MM;     // [BSZ,1,DD]

    cudaFuncSetAttribute(attn_gemm_hmma,
                         cudaFuncAttributeMaxDynamicSharedMemorySize, SMEM_TOTAL);

    prep_b_kernel<<<HH, 128>>>(Wm);
    qproj_kernel<<<dim3(BSZ, HH / 128), 128>>>(query, Wq, bq);
    attn_gemm_hmma<<<dim3(HT, (BSZ * MM) / 128), 256, SMEM_TOTAL>>>(memory, v);
    softmax_kernel<<<BSZ, 256>>>(out_weights);
    weighted_mem_kernel<<<dim3(DD / 128, BSZ), 256>>>(memory, out_weights, out_wmem);
}